// round 1
// baseline (speedup 1.0000x reference)
#include <cuda_runtime.h>
#include <cstdint>

#define NN 16384
#define HH 2048
#define KN 25
#define CHUNK 128
#define NCHUNK (HH / CHUNK)
#define RPW 4
#define NWARPS 4
#define RPB (RPW * NWARPS)
#define NTHREADS (NWARPS * 32)

__device__ __forceinline__ void cp_async16(uint32_t saddr, const void* gptr) {
    asm volatile("cp.async.cg.shared.global [%0], [%1], 16;" :: "r"(saddr), "l"(gptr));
}

__global__ __launch_bounds__(NTHREADS, 2)
void nce_kernel(const float* __restrict__ input,
                const float* __restrict__ weight,
                const float* __restrict__ bias,
                const float* __restrict__ unig,
                const int* __restrict__ target,
                const int* __restrict__ noise,
                float* __restrict__ out)
{
    __shared__ __align__(16) float sw[2][KN][CHUNK];  // 25.6 KB double-buffered noise tile
    __shared__ int s_noise[KN];
    __shared__ float s_nb[KN], s_nu[KN];

    const int tid  = threadIdx.x;
    const int lane = tid & 31;
    const int wid  = tid >> 5;
    const int rb   = blockIdx.x * RPB;      // first row of this block
    const int row0 = rb + wid * RPW;        // first row of this warp

    if (tid < KN) {
        int nk = noise[tid];
        s_noise[tid] = nk;
        s_nb[tid] = bias[nk];
        s_nu[tid] = unig[nk];
    }
    __syncthreads();

    // ---- early independent outputs: pnn (broadcast) and pnt (gathered unigram) ----
    {
        const size_t pnn_base = (size_t)2 * NN + (size_t)NN * KN + (size_t)rb * KN;
        #pragma unroll 1
        for (int i = tid; i < RPB * KN; i += NTHREADS)
            out[pnn_base + i] = s_nu[i % KN];
        if (tid < RPB) {
            int n = rb + tid;
            out[NN + n] = unig[target[n]];
        }
    }

    int tgt[RPW];
    const float4* xp[RPW];
    const float4* wtp[RPW];
    #pragma unroll
    for (int r = 0; r < RPW; r++) {
        int n = row0 + r;
        tgt[r] = target[n];
        xp[r]  = reinterpret_cast<const float4*>(input)  + (size_t)n * (HH / 4);
        wtp[r] = reinterpret_cast<const float4*>(weight) + (size_t)tgt[r] * (HH / 4);
    }

    float acc[RPW][KN];
    float acct[RPW];
    #pragma unroll
    for (int r = 0; r < RPW; r++) {
        acct[r] = 0.f;
        #pragma unroll
        for (int k = 0; k < KN; k++) acc[r][k] = 0.f;
    }

    // cp.async loader for one 25x128 noise-weight chunk
    auto load_chunk = [&](int c, int buf) {
        uint32_t sbase = (uint32_t)__cvta_generic_to_shared(&sw[buf][0][0]);
        #pragma unroll 1
        for (int i = tid; i < KN * (CHUNK / 4); i += NTHREADS) {
            int k = i >> 5;   // CHUNK/4 == 32
            int j = i & 31;
            const float4* g = reinterpret_cast<const float4*>(weight)
                              + (size_t)s_noise[k] * (HH / 4) + c * (CHUNK / 4) + j;
            cp_async16(sbase + (uint32_t)(i * 16), g);
        }
        asm volatile("cp.async.commit_group;" ::: "memory");
    };

    load_chunk(0, 0);

    // register prefetch of input + target-weight for chunk 0
    float4 x[RPW], wt[RPW];
    #pragma unroll
    for (int r = 0; r < RPW; r++) { x[r] = xp[r][lane]; wt[r] = wtp[r][lane]; }

    #pragma unroll 1
    for (int c = 0; c < NCHUNK; c++) {
        const int nb = c & 1;
        asm volatile("cp.async.wait_group 0;" ::: "memory");
        __syncthreads();                       // chunk c visible block-wide; prev compute done
        if (c + 1 < NCHUNK) load_chunk(c + 1, nb ^ 1);

        float4 xn[RPW], wtn[RPW];
        if (c + 1 < NCHUNK) {
            #pragma unroll
            for (int r = 0; r < RPW; r++) {
                int idx = (c + 1) * (CHUNK / 4) + lane;
                xn[r]  = xp[r][idx];
                wtn[r] = wtp[r][idx];
            }
        }

        const float4* wrow = reinterpret_cast<const float4*>(&sw[nb][0][0]) + lane;
        #pragma unroll
        for (int k = 0; k < KN; k++) {
            float4 w = wrow[k * (CHUNK / 4)];
            #pragma unroll
            for (int r = 0; r < RPW; r++) {
                float a = acc[r][k];
                a = fmaf(x[r].x, w.x, a);
                a = fmaf(x[r].y, w.y, a);
                a = fmaf(x[r].z, w.z, a);
                a = fmaf(x[r].w, w.w, a);
                acc[r][k] = a;
            }
        }
        #pragma unroll
        for (int r = 0; r < RPW; r++) {
            float a = acct[r];
            a = fmaf(x[r].x, wt[r].x, a);
            a = fmaf(x[r].y, wt[r].y, a);
            a = fmaf(x[r].z, wt[r].z, a);
            a = fmaf(x[r].w, wt[r].w, a);
            acct[r] = a;
        }

        if (c + 1 < NCHUNK) {
            #pragma unroll
            for (int r = 0; r < RPW; r++) { x[r] = xn[r]; wt[r] = wtn[r]; }
        }
    }

    // ---- warp butterfly reduction over lanes (each lane held a disjoint H slice) ----
    #pragma unroll
    for (int off = 16; off > 0; off >>= 1) {
        #pragma unroll
        for (int r = 0; r < RPW; r++) {
            acct[r] += __shfl_xor_sync(0xffffffffu, acct[r], off);
            #pragma unroll
            for (int k = 0; k < KN; k++)
                acc[r][k] += __shfl_xor_sync(0xffffffffu, acc[r][k], off);
        }
    }

    // ---- outputs: pmn via predicated constant-index stores (no local-mem spill), pmt ----
    #pragma unroll
    for (int r = 0; r < RPW; r++) {
        const int n = row0 + r;
        float* pmn_row = out + (size_t)2 * NN + (size_t)n * KN;
        #pragma unroll
        for (int k = 0; k < KN; k++) {
            if (lane == k) pmn_row[k] = expf(acc[r][k] + s_nb[k]);
        }
        if (lane == KN) {
            out[n] = expf(acct[r] + bias[tgt[r]]);
        }
    }
}

extern "C" void kernel_launch(void* const* d_in, const int* in_sizes, int n_in,
                              void* d_out, int out_size) {
    const float* input  = (const float*)d_in[0];
    const float* weight = (const float*)d_in[1];
    const float* bias   = (const float*)d_in[2];
    const float* unig   = (const float*)d_in[3];
    const int*   target = (const int*)d_in[4];
    const int*   noise  = (const int*)d_in[5];
    float* out = (float*)d_out;

    nce_kernel<<<NN / RPB, NTHREADS>>>(input, weight, bias, unig, target, noise, out);
}